// round 13
// baseline (speedup 1.0000x reference)
#include <cuda_runtime.h>
#include <cstdint>

// Shapes: x[8,64,512,512] f32, W[64,64], b[64], seg_w[4,4] -> out[8,64,512,512]
// SEG=4 -> 128x128 blocks. A "band" = one (b,c,i) slab of 128 rows = 16384 float4.
// 2048 bands. Measured: read 6.94 TB/s (pool 77.9us), write 6.11 TB/s
// (bcast 78.0us), fixed harness overhead ~16us.
// Structure: pool grid = 2048 streaming CTAs + 8 waiter CTAs that compute the
// per-batch linear as soon as that batch's pools are done (hides the linear).
#define Bb 8
#define Cc 64
#define Oo 64
#define BAND_F4 16384
#define NBAND   2048

// scratch (__device__ globals: allocation-free rule)
__device__ float g_pooled[Bb*Cc*16];     // [b][c][i*4+j], mean-scaled
__device__ float g_weighted[Bb*Oo*16];   // [b][o][i*4+j]
__device__ int   g_cnt[Bb];              // per-batch pool arrival counters

// ---------------------------------------------------------------------------
// Kernel 1: pool (+ 8 waiter CTAs running the tiny linear).
// blockIdx < 2048 : R1's exact pool body; tid0 appends fence+count AFTER the
//                   pooled stores, gating nobody's exit.
// blockIdx >= 2048: waiter for batch b = blockIdx-2048; spins until all 256
//                   pool CTAs of batch b arrived, then computes 64x16 linear.
// ---------------------------------------------------------------------------
__global__ __launch_bounds__(256) void pool_kernel(
    const float4* __restrict__ x,
    const float*  __restrict__ Wm,
    const float*  __restrict__ bias,
    const float*  __restrict__ segw)
{
    const int tid = threadIdx.x;

    if (blockIdx.x >= NBAND) {
        // ---- waiter CTA: linear for batch b once its 256 pools are in
        const int b = blockIdx.x - NBAND;
        if (tid == 0) {
            while (*(volatile int*)&g_cnt[b] != 256) __nanosleep(256);
        }
        __syncthreads();
        __threadfence();                          // acquire pooled values

        #pragma unroll
        for (int k = 0; k < 4; k++) {
            const int idx2 = tid + k * 256;       // 0..1023
            const int o = idx2 >> 4, ij = idx2 & 15;
            const float* p  = g_pooled + (b * Cc) * 16 + ij;
            const float* wr = Wm + o * Cc;
            float a = bias[o];
            #pragma unroll 8
            for (int c = 0; c < Cc; c++)
                a = fmaf(__ldcg(&p[c * 16]), wr[c], a);
            g_weighted[(b * Oo + o) * 16 + ij] = a * segw[ij];
        }
        return;
    }

    // ---- pool CTA: R1's exact streaming body
    const int g = blockIdx.x;                     // band index 0..2047
    const float4* base = x + (size_t)g * BAND_F4;

    float acc = 0.0f;
    #pragma unroll 8
    for (int idx = tid; idx < BAND_F4; idx += 256) {
        float4 v = base[idx];
        acc += (v.x + v.y) + (v.z + v.w);
    }

    #pragma unroll
    for (int off = 16; off; off >>= 1)
        acc += __shfl_xor_sync(0xffffffffu, acc, off);

    __shared__ float ws[8];
    const int warp = tid >> 5;
    if ((tid & 31) == 0) ws[warp] = acc;          // warp w covers j = w&3
    __syncthreads();

    if (tid == 0) {
        const float inv = 1.0f / 16384.0f;
        float* dst = g_pooled + (g >> 2) * 16 + (g & 3) * 4;
        dst[0] = (ws[0] + ws[4]) * inv;
        dst[1] = (ws[1] + ws[5]) * inv;
        dst[2] = (ws[2] + ws[6]) * inv;
        dst[3] = (ws[3] + ws[7]) * inv;
        __threadfence();                          // release pooled values
        atomicAdd(&g_cnt[g >> 8], 1);             // batch = band/256
    }
    // all other threads exit immediately -- no exit gating
}

// ---------------------------------------------------------------------------
// Kernel 2: broadcast (R1's exact body, 78.0us measured). One CTA per band
// (b,o,i); thread's column segment j loop-invariant; pure float4 streaming.
// Also resets g_cnt for the next graph replay (pool is quiescent now).
// ---------------------------------------------------------------------------
__global__ __launch_bounds__(256) void bcast_kernel(float4* __restrict__ out)
{
    if (blockIdx.x == 0 && threadIdx.x < Bb) g_cnt[threadIdx.x] = 0;

    const int g  = blockIdx.x;                    // band index 0..2047
    const int bo = g >> 2;                        // b*O + o
    const int i  = g & 3;

    const float* wv = g_weighted + bo * 16 + i * 4;
    const int j = (threadIdx.x & 127) >> 5;       // fixed per thread
    const float v = wv[j];
    const float4 f = make_float4(v, v, v, v);

    float4* base = out + (size_t)bo * (4 * BAND_F4) + (size_t)i * BAND_F4;

    #pragma unroll 8
    for (int idx = threadIdx.x; idx < BAND_F4; idx += 256)
        base[idx] = f;
}

// ---------------------------------------------------------------------------
extern "C" void kernel_launch(void* const* d_in, const int* in_sizes, int n_in,
                              void* d_out, int out_size)
{
    const float4* x    = (const float4*)d_in[0];
    const float*  Wm   = (const float*)d_in[1];
    const float*  bias = (const float*)d_in[2];
    const float*  segw = (const float*)d_in[3];
    float4* out = (float4*)d_out;

    pool_kernel<<<NBAND + Bb, 256>>>(x, Wm, bias, segw);
    bcast_kernel<<<NBAND, 256>>>(out);
}

// round 14
// speedup vs baseline: 1.0134x; 1.0134x over previous
#include <cuda_runtime.h>
#include <cstdint>

// Shapes: x[8,64,512,512] f32, W[64,64], b[64], seg_w[4,4] -> out[8,64,512,512]
// SEG=4 -> 128x128 blocks. A "band" = one (b,c,i) slab of 128 rows = 16384 float4.
// 2048 bands. Measured: fence-free pool 77.9us (6.94 TB/s), bcast 78-79us
// (6.1 TB/s), ~16us fixed harness overhead. __threadfence() => CCTL.IVALL
// (L1D flush) killed every fused pool variant (+14us); this version uses
// red.release / ld.acquire (L2-ordered, NO L1 flush) instead.
#define Bb 8
#define Cc 64
#define Oo 64
#define BAND_F4 16384
#define NBAND   2048

// scratch (__device__ globals: allocation-free rule)
__device__ __align__(16) float g_pooled[Bb*Cc*16];   // [b][c][i*4+j], mean-scaled
__device__ float g_weighted[Bb*Oo*16];               // [b][o][i*4+j]
__device__ int   g_cnt[Bb];                          // per-batch arrival counters

__device__ __forceinline__ void red_release_add(int* addr, int val) {
    asm volatile("red.release.gpu.global.add.s32 [%0], %1;"
                 :: "l"(addr), "r"(val) : "memory");
}
__device__ __forceinline__ int ld_acquire(const int* addr) {
    int v;
    asm volatile("ld.acquire.gpu.global.s32 %0, [%1];"
                 : "=r"(v) : "l"(addr) : "memory");
    return v;
}

// ---------------------------------------------------------------------------
// Kernel 1: pool (+ 8 waiter CTAs computing the tiny linear).
// blockIdx < 2048 : R1's exact streaming body; tid0 appends one float4 store
//                   and one red.release (no fence, no L1 flush, no exit gating).
// blockIdx >= 2048: waiter for batch b; acquire-polls the counter, then
//                   computes the 64x16 linear from L2 (__ldcg).
// ---------------------------------------------------------------------------
__global__ __launch_bounds__(256) void pool_kernel(
    const float4* __restrict__ x,
    const float*  __restrict__ Wm,
    const float*  __restrict__ bias,
    const float*  __restrict__ segw)
{
    const int tid = threadIdx.x;

    if (blockIdx.x >= NBAND) {
        // ---- waiter CTA: linear for batch b once its 256 pools arrived
        const int b = blockIdx.x - NBAND;
        if (tid == 0) {
            while (ld_acquire(&g_cnt[b]) != 256) __nanosleep(256);
        }
        __syncthreads();

        #pragma unroll
        for (int k = 0; k < 4; k++) {
            const int idx2 = tid + k * 256;          // 0..1023
            const int o = idx2 >> 4, ij = idx2 & 15;
            const float* p  = g_pooled + (b * Cc) * 16 + ij;
            const float* wr = Wm + o * Cc;
            float a = bias[o];
            #pragma unroll 8
            for (int c = 0; c < Cc; c++)
                a = fmaf(__ldcg(&p[c * 16]), wr[c], a);
            g_weighted[(b * Oo + o) * 16 + ij] = a * segw[ij];
        }
        return;
    }

    // ---- pool CTA: R1's exact streaming body
    const int g = blockIdx.x;                        // band index 0..2047
    const float4* base = x + (size_t)g * BAND_F4;

    float acc = 0.0f;
    #pragma unroll 8
    for (int idx = tid; idx < BAND_F4; idx += 256) {
        float4 v = base[idx];
        acc += (v.x + v.y) + (v.z + v.w);
    }

    #pragma unroll
    for (int off = 16; off; off >>= 1)
        acc += __shfl_xor_sync(0xffffffffu, acc, off);

    __shared__ float ws[8];
    const int warp = tid >> 5;
    if ((tid & 31) == 0) ws[warp] = acc;             // warp w covers j = w&3
    __syncthreads();

    if (tid == 0) {
        const float inv = 1.0f / 16384.0f;
        float4 r = make_float4((ws[0] + ws[4]) * inv,
                               (ws[1] + ws[5]) * inv,
                               (ws[2] + ws[6]) * inv,
                               (ws[3] + ws[7]) * inv);
        // cell base (g>>2)*16 + (g&3)*4 is 16B aligned
        *reinterpret_cast<float4*>(&g_pooled[(g >> 2) * 16 + (g & 3) * 4]) = r;
        red_release_add(&g_cnt[g >> 8], 1);          // release: orders the store
    }
    // everyone else exits immediately
}

// ---------------------------------------------------------------------------
// Kernel 2: broadcast (R1's body, evict-first stores). One CTA per band
// (b,o,i); thread's column segment j loop-invariant; pure float4 streaming.
// Also resets g_cnt for the next graph replay (pool is quiescent now).
// ---------------------------------------------------------------------------
__global__ __launch_bounds__(256) void bcast_kernel(float4* __restrict__ out)
{
    if (blockIdx.x == 0 && threadIdx.x < Bb) g_cnt[threadIdx.x] = 0;

    const int g  = blockIdx.x;                       // band index 0..2047
    const int bo = g >> 2;                           // b*O + o
    const int i  = g & 3;

    const float* wv = g_weighted + bo * 16 + i * 4;
    const int j = (threadIdx.x & 127) >> 5;          // fixed per thread
    const float v = wv[j];
    const float4 f = make_float4(v, v, v, v);

    float4* base = out + (size_t)bo * (4 * BAND_F4) + (size_t)i * BAND_F4;

    #pragma unroll 8
    for (int idx = threadIdx.x; idx < BAND_F4; idx += 256)
        __stcs(&base[idx], f);
}

// ---------------------------------------------------------------------------
extern "C" void kernel_launch(void* const* d_in, const int* in_sizes, int n_in,
                              void* d_out, int out_size)
{
    const float4* x    = (const float4*)d_in[0];
    const float*  Wm   = (const float*)d_in[1];
    const float*  bias = (const float*)d_in[2];
    const float*  segw = (const float*)d_in[3];
    float4* out = (float4*)d_out;

    pool_kernel<<<NBAND + Bb, 256>>>(x, Wm, bias, segw);
    bcast_kernel<<<NBAND, 256>>>(out);
}